// round 14
// baseline (speedup 1.0000x reference)
#include <cuda_runtime.h>
#include <math.h>

#define BB   8
#define CC   64
#define CR   8
#define HH   64
#define WWD  64
#define NPIX 4096   // HH*WWD
#define NBLK 256    // 2 CTAs/SM co-resident (256 <= 148*2); = BB*32 chunks
#define NTHR 512

// ---------------- device scratch (static, no allocation) ----------------
__device__ float d_avg[BB * CC];
__device__ float d_maxv[BB * CC];
__device__ float d_sa_avg[BB * NPIX];
__device__ float d_sa_max[BB * NPIX];
// PAM fallback scratch (only written when gamma != 0)
__device__ float d_q[BB * CR * NPIX];
__device__ float d_k[BB * CR * NPIX];
__device__ float d_v[BB * CC * NPIX];
__device__ __align__(16) float d_pam[BB * CC * NPIX];
// grid barrier ticket counter (monotonic; safe across graph replays)
__device__ unsigned long long g_bar;

// All NBLK blocks are co-resident (2 CTAs/SM by __launch_bounds__(512,2);
// regs<=64, smem ~30KB/CTA), so spinning is deadlock-free.
__device__ __forceinline__ void grid_barrier() {
    __syncthreads();
    if (threadIdx.x == 0) {
        __threadfence();
        const unsigned long long t = atomicAdd(&g_bar, 1ULL);
        const unsigned long long release = (t / NBLK + 1ULL) * (unsigned long long)NBLK;
        volatile unsigned long long* p = &g_bar;
        while (*p < release) { }
    }
    __syncthreads();
}

__global__ void __launch_bounds__(NTHR, 2)
k_pcbam(const float* __restrict__ x,
        const float* __restrict__ fc1,   // [CR, C]
        const float* __restrict__ fc2,   // [C, CR]
        const float* __restrict__ qw, const float* __restrict__ qbias,
        const float* __restrict__ kw, const float* __restrict__ kbias,
        const float* __restrict__ vw, const float* __restrict__ vbias,
        const float* __restrict__ gamma,
        const float* __restrict__ sw,    // [2,7,7]
        float* __restrict__ out) {
    const int blk = blockIdx.x;   // 0..255
    const int t   = threadIdx.x;  // 0..511
    const int b     = blk >> 5;   // batch
    const int chunk = blk & 31;   // 2-row chunk
    const int n0    = chunk << 7; // first pixel (128 px per chunk)
    const int h0    = chunk << 1; // first row

    // dynamic smem 20 KB: PAM fallback att[4096]+red[512] (g!=0 only).
    extern __shared__ __align__(16) float dyn[];
    float* att = dyn;            // fallback only [4096]
    float* red = dyn + NPIX;     // fallback only [512]

    __shared__ float red_s[16], red_m[16];
    __shared__ float s_sum[CC], s_max[CC], ca[CC];
    __shared__ float h_avg[CR], h_mx[CR];
    __shared__ float ps[4][128], pm[4][128];
    __shared__ float tile_avg[8][70], tile_max[8][70];   // rows h0-3 .. h0+4
    __shared__ float wgt[98];
    __shared__ __align__(16) float mask_s[128];

    const float g = gamma[0];
    const int wid = t >> 5, lid = t & 31;

    // ================= Phase A: per-(b,c) mean & max over HW =================
    // 512 rows / 256 blocks = 2 rows/block; one row per 256-thread group.
    {
        const int row  = t >> 8;        // 0..1
        const int rtid = t & 255;
        const int bc   = blk * 2 + row;
        const float4* xp = reinterpret_cast<const float4*>(x + (size_t)bc * NPIX);
        float s = 0.0f, m = -INFINITY;
        #pragma unroll
        for (int j = 0; j < 4; j++) {
            const float4 v = xp[rtid + j * 256];
            s += (v.x + v.y) + (v.z + v.w);
            m = fmaxf(m, fmaxf(fmaxf(v.x, v.y), fmaxf(v.z, v.w)));
        }
        #pragma unroll
        for (int off = 16; off; off >>= 1) {
            s += __shfl_down_sync(0xffffffffu, s, off);
            m  = fmaxf(m, __shfl_down_sync(0xffffffffu, m, off));
        }
        if (lid == 0) { red_s[wid] = s; red_m[wid] = m; }
        __syncthreads();
        if (rtid == 0) {
            float ts = 0.0f, tm = -INFINITY;
            #pragma unroll
            for (int w = 0; w < 8; w++) {
                ts += red_s[row * 8 + w];
                tm = fmaxf(tm, red_m[row * 8 + w]);
            }
            d_avg[bc]  = ts * (1.0f / NPIX);
            d_maxv[bc] = tm;
        }
    }

    grid_barrier();

    // ================= Phase B: MLP + spatial stats (own 2 rows) =============
    if (t < 64)            s_sum[t]      = __ldcg(&d_avg[b * CC + t]);
    else if (t < 128)      s_max[t - 64] = __ldcg(&d_maxv[b * CC + t - 64]);
    else if (t < 226)      wgt[t - 128]  = sw[t - 128];
    __syncthreads();
    if (t < CR) {
        float ha = 0.0f, hm = 0.0f;
        #pragma unroll
        for (int c = 0; c < CC; c++) {
            const float w = fc1[t * CC + c];
            ha += s_sum[c] * w;
            hm += s_max[c] * w;
        }
        h_avg[t] = fmaxf(ha, 0.0f);
        h_mx[t]  = fmaxf(hm, 0.0f);
    }
    __syncthreads();
    if (t < CC) {
        float o = 0.0f;
        #pragma unroll
        for (int r = 0; r < CR; r++)
            o += (h_avg[r] + h_mx[r]) * fc2[t * CR + r];
        ca[t] = 1.0f / (1.0f + __expf(-o));
    }
    __syncthreads();
    {
        const int px  = t & 127;        // lane-contiguous pixels
        const int grp = t >> 7;         // 4 channel groups of 16
        const float* xb = x + (size_t)b * CC * NPIX + n0 + px;
        float s = 0.0f, m = -INFINITY;
        #pragma unroll
        for (int cc = 0; cc < 16; cc++) {
            const int c = grp * 16 + cc;
            const float v = __ldg(&xb[c * NPIX]) * ca[c];
            s += v;
            m = fmaxf(m, v);
        }
        ps[grp][px] = s;
        pm[grp][px] = m;
        __syncthreads();
        if (t < 128) {
            const float ts = (ps[0][t] + ps[1][t] + ps[2][t] + ps[3][t]) * (1.0f / CC);
            const float tm = fmaxf(fmaxf(pm[0][t], pm[1][t]), fmaxf(pm[2][t], pm[3][t]));
            d_sa_avg[b * NPIX + n0 + t] = ts;
            d_sa_max[b * NPIX + n0 + t] = tm;
        }
    }

    // ============ PAM fallback (uniform branch; benchmark: g==0) =============
    if (g != 0.0f) {
        grid_barrier();
        for (int bn = blk * NTHR + t; bn < BB * NPIX; bn += NBLK * NTHR) {
            const int bb = bn >> 12, n = bn & (NPIX - 1);
            const float* xb = x + (size_t)bb * CC * NPIX + n;
            float qa[CR], ka[CR];
            #pragma unroll
            for (int r = 0; r < CR; r++) { qa[r] = qbias[r]; ka[r] = kbias[r]; }
            for (int c = 0; c < CC; c++) {
                const float xv = xb[c * NPIX];
                #pragma unroll
                for (int r = 0; r < CR; r++) {
                    qa[r] += xv * qw[r * CC + c];
                    ka[r] += xv * kw[r * CC + c];
                }
            }
            #pragma unroll
            for (int r = 0; r < CR; r++) {
                d_q[(bb * CR + r) * NPIX + n] = qa[r];
                d_k[(bb * CR + r) * NPIX + n] = ka[r];
            }
        }
        for (int bcn = blk * NTHR + t; bcn < BB * CC * NPIX; bcn += NBLK * NTHR) {
            const int bc = bcn >> 12;
            const int bb = bc >> 6, c = bc & 63, n = bcn & (NPIX - 1);
            const float* xb = x + (size_t)bb * CC * NPIX + n;
            float acc = vbias[c];
            for (int cc = 0; cc < CC; cc++) acc += xb[cc * NPIX] * vw[c * CC + cc];
            d_v[bcn] = acc;
        }
        grid_barrier();
        for (int row = blk; row < BB * NPIX; row += NBLK) {
            const int bb = row >> 12;
            const int i  = row & (NPIX - 1);
            float qr[CR];
            #pragma unroll
            for (int r = 0; r < CR; r++) qr[r] = __ldcg(&d_q[(bb * CR + r) * NPIX + i]);
            float mx = -INFINITY;
            for (int j = t; j < NPIX; j += NTHR) {
                float e = 0.0f;
                #pragma unroll
                for (int r = 0; r < CR; r++) e += qr[r] * __ldcg(&d_k[(bb * CR + r) * NPIX + j]);
                att[j] = e;
                mx = fmaxf(mx, e);
            }
            red[t] = mx; __syncthreads();
            for (int s = NTHR / 2; s; s >>= 1) {
                if (t < s) red[t] = fmaxf(red[t], red[t + s]);
                __syncthreads();
            }
            mx = red[0]; __syncthreads();
            float sum = 0.0f;
            for (int j = t; j < NPIX; j += NTHR) {
                const float e = expf(att[j] - mx);
                att[j] = e;
                sum += e;
            }
            red[t] = sum; __syncthreads();
            for (int s = NTHR / 2; s; s >>= 1) {
                if (t < s) red[t] += red[t + s];
                __syncthreads();
            }
            const float inv = 1.0f / red[0]; __syncthreads();
            for (int c = 0; c < CC; c++) {
                float acc = 0.0f;
                for (int j = t; j < NPIX; j += NTHR)
                    acc += att[j] * __ldcg(&d_v[(bb * CC + c) * NPIX + j]);
                red[t] = acc; __syncthreads();
                for (int s = NTHR / 2; s; s >>= 1) {
                    if (t < s) red[t] += red[t + s];
                    __syncthreads();
                }
                if (t == 0) d_pam[(bb * CC + c) * NPIX + i] = red[0] * inv;
                __syncthreads();
            }
        }
    }

    grid_barrier();

    // ============ Phase C: halo + 7x7 conv + sigmoid + final combine =========
    // tile rows h0-3 .. h0+4 (8 rows), cols -3..66
    for (int i = t; i < 560; i += NTHR) {
        const int r = i / 70, cidx = i % 70;
        const int gh = h0 - 3 + r, gw = cidx - 3;
        float a = 0.0f, mv = 0.0f;
        if ((unsigned)gh < (unsigned)HH && (unsigned)gw < (unsigned)WWD) {
            const int gi = b * NPIX + gh * WWD + gw;
            a  = __ldcg(&d_sa_avg[gi]);
            mv = __ldcg(&d_sa_max[gi]);
        }
        tile_avg[r][cidx] = a;
        tile_max[r][cidx] = mv;
    }
    __syncthreads();
    if (t < 128) {
        const int h = t >> 6, w = t & 63;
        float acc = 0.0f;
        #pragma unroll
        for (int kh = 0; kh < 7; kh++)
            #pragma unroll
            for (int kw2 = 0; kw2 < 7; kw2++)
                acc += tile_avg[h + kh][w + kw2] * wgt[kh * 7 + kw2]
                     + tile_max[h + kh][w + kw2] * wgt[49 + kh * 7 + kw2];
        mask_s[t] = 1.0f / (1.0f + __expf(-acc));
    }
    __syncthreads();
    {
        const int px4 = t & 31;     // float4 index within 128-px chunk
        const int c0  = t >> 5;     // 0..15
        const float4 m4 = reinterpret_cast<const float4*>(mask_s)[px4];
        const size_t base4 = (size_t)b * CC * (NPIX / 4) + (size_t)(n0 >> 2) + px4;
        if (g == 0.0f) {
            #pragma unroll
            for (int k = 0; k < 4; k++) {
                const int c = c0 + 16 * k;
                const size_t idx4 = base4 + (size_t)c * (NPIX / 4);
                const float4 xv = reinterpret_cast<const float4*>(x)[idx4];
                const float cav = ca[c];
                float4 o;
                o.x = xv.x * (1.0f + cav * m4.x);
                o.y = xv.y * (1.0f + cav * m4.y);
                o.z = xv.z * (1.0f + cav * m4.z);
                o.w = xv.w * (1.0f + cav * m4.w);
                reinterpret_cast<float4*>(out)[idx4] = o;
            }
        } else {
            #pragma unroll
            for (int k = 0; k < 4; k++) {
                const int c = c0 + 16 * k;
                const size_t idx4 = base4 + (size_t)c * (NPIX / 4);
                const float4 xv = reinterpret_cast<const float4*>(x)[idx4];
                const float4 pv = reinterpret_cast<const float4*>(d_pam)[idx4];
                const float cav = ca[c];
                float4 o;
                o.x = xv.x * (1.0f + cav * m4.x) + g * pv.x;
                o.y = xv.y * (1.0f + cav * m4.y) + g * pv.y;
                o.z = xv.z * (1.0f + cav * m4.z) + g * pv.z;
                o.w = xv.w * (1.0f + cav * m4.w) + g * pv.w;
                reinterpret_cast<float4*>(out)[idx4] = o;
            }
        }
    }
}

// ---------------- launch ----------------
extern "C" void kernel_launch(void* const* d_in, const int* in_sizes, int n_in,
                              void* d_out, int out_size) {
    const float* x     = (const float*)d_in[0];
    const float* fc1_w = (const float*)d_in[1];
    const float* fc2_w = (const float*)d_in[2];
    const float* q_w   = (const float*)d_in[3];
    const float* q_b   = (const float*)d_in[4];
    const float* k_w   = (const float*)d_in[5];
    const float* k_b   = (const float*)d_in[6];
    const float* v_w   = (const float*)d_in[7];
    const float* v_b   = (const float*)d_in[8];
    const float* gamma = (const float*)d_in[9];
    const float* sa_w  = (const float*)d_in[10];
    float* out = (float*)d_out;

    const int dyn_bytes = (NPIX + NTHR) * (int)sizeof(float);   // 18 KB
    k_pcbam<<<NBLK, NTHR, dyn_bytes>>>(x, fc1_w, fc2_w, q_w, q_b, k_w, k_b,
                                       v_w, v_b, gamma, sa_w, out);
}

// round 15
// speedup vs baseline: 1.0334x; 1.0334x over previous
#include <cuda_runtime.h>
#include <math.h>

#define BB   8
#define CC   64
#define CR   8
#define HH   64
#define WWD  64
#define NPIX 4096   // HH*WWD
#define NBLK 128    // persistent grid: must be <= SM count (148)
#define NTHR 1024

// ---------------- device scratch (static, no allocation) ----------------
__device__ float d_avg[BB * CC];
__device__ float d_maxv[BB * CC];
__device__ float d_sa_avg[BB * NPIX];
__device__ float d_sa_max[BB * NPIX];
// PAM fallback scratch (only written when gamma != 0)
__device__ float d_q[BB * CR * NPIX];
__device__ float d_k[BB * CR * NPIX];
__device__ float d_v[BB * CC * NPIX];
__device__ __align__(16) float d_pam[BB * CC * NPIX];
// grid barrier ticket counter (monotonic; safe across graph replays)
__device__ unsigned long long g_bar;

// Software grid barrier. All NBLK blocks are co-resident (NBLK <= #SMs, 1 CTA
// each), so spinning is deadlock-free. Monotonic ticket scheme: no reset needed.
__device__ __forceinline__ void grid_barrier() {
    __syncthreads();
    if (threadIdx.x == 0) {
        __threadfence();
        const unsigned long long t = atomicAdd(&g_bar, 1ULL);
        const unsigned long long release = (t / NBLK + 1ULL) * (unsigned long long)NBLK;
        volatile unsigned long long* p = &g_bar;
        while (*p < release) { }
    }
    __syncthreads();
}

__global__ void __launch_bounds__(NTHR, 1)
k_pcbam(const float* __restrict__ x,
        const float* __restrict__ fc1,   // [CR, C]
        const float* __restrict__ fc2,   // [C, CR]
        const float* __restrict__ qw, const float* __restrict__ qbias,
        const float* __restrict__ kw, const float* __restrict__ kbias,
        const float* __restrict__ vw, const float* __restrict__ vbias,
        const float* __restrict__ gamma,
        const float* __restrict__ sw,    // [2,7,7]
        float* __restrict__ out) {
    const int blk = blockIdx.x;   // 0..127
    const int t   = threadIdx.x;  // 0..1023

    __shared__ float red_s[32], red_m[32];          // per-warp partials (phase A)
    __shared__ float ca[CC], h_avg[CR], h_mx[CR];
    __shared__ float ps[4][256], pm[4][256];        // phase B partials
    __shared__ float s_avg[10][70], s_max[10][70];
    __shared__ float wgt[98];
    __shared__ __align__(16) float mask[256];
    __shared__ float att[NPIX];    // PAM fallback only
    __shared__ float red[NTHR];    // PAM fallback only

    const float g = gamma[0];
    const int wid = t >> 5, lid = t & 31;

    // ================= Phase A: per-(b,c) mean & max over HW =================
    // 512 rows / 128 blocks = 4 rows/block; one row per 256-thread group.
    {
        const int row  = t >> 8;        // 0..3
        const int rtid = t & 255;       // thread within row-group
        const int bc   = blk * 4 + row;
        const float4* xp = reinterpret_cast<const float4*>(x + (size_t)bc * NPIX);
        float s = 0.0f, m = -INFINITY;
        #pragma unroll
        for (int j = 0; j < 4; j++) {
            const float4 v = xp[rtid + j * 256];
            s += (v.x + v.y) + (v.z + v.w);
            m = fmaxf(m, fmaxf(fmaxf(v.x, v.y), fmaxf(v.z, v.w)));
        }
        #pragma unroll
        for (int off = 16; off; off >>= 1) {
            s += __shfl_down_sync(0xffffffffu, s, off);
            m  = fmaxf(m, __shfl_down_sync(0xffffffffu, m, off));
        }
        if (lid == 0) { red_s[wid] = s; red_m[wid] = m; }
        __syncthreads();
        if (rtid == 0) {          // one thread per row-group (wid = row*8)
            float ts = 0.0f, tm = -INFINITY;
            #pragma unroll
            for (int w = 0; w < 8; w++) {
                ts += red_s[row * 8 + w];
                tm = fmaxf(tm, red_m[row * 8 + w]);
            }
            d_avg[bc]  = ts * (1.0f / NPIX);
            d_maxv[bc] = tm;
        }
    }

    grid_barrier();

    // ================= Phase B: fused MLP + spatial stats =================
    const int b     = blk >> 4;          // batch
    const int chunk = blk & 15;          // 256-pixel chunk
    const int n0    = chunk << 8;

    if (t < CR) {
        float ha = 0.0f, hm = 0.0f;
        #pragma unroll
        for (int c = 0; c < CC; c++) {
            const float w = fc1[t * CC + c];
            ha += __ldcg(&d_avg[b * CC + c])  * w;
            hm += __ldcg(&d_maxv[b * CC + c]) * w;
        }
        h_avg[t] = fmaxf(ha, 0.0f);
        h_mx[t]  = fmaxf(hm, 0.0f);
    }
    __syncthreads();
    if (t < CC) {
        float o = 0.0f;
        #pragma unroll
        for (int r = 0; r < CR; r++)
            o += (h_avg[r] + h_mx[r]) * fc2[t * CR + r];
        ca[t] = 1.0f / (1.0f + __expf(-o));
    }
    __syncthreads();
    {
        const int px  = t & 255;        // pixel within chunk
        const int grp = t >> 8;         // channel group 0..3 (16 ch each)
        const int n   = n0 + px;
        const float* xb = x + (size_t)b * CC * NPIX + n;
        float s = 0.0f, m = -INFINITY;
        #pragma unroll
        for (int cc = 0; cc < 16; cc++) {
            const int c = grp * 16 + cc;
            const float v = xb[c * NPIX] * ca[c];
            s += v;
            m = fmaxf(m, v);
        }
        ps[grp][px] = s;
        pm[grp][px] = m;
        __syncthreads();
        if (t < 256) {
            float ts = ps[0][t] + ps[1][t] + ps[2][t] + ps[3][t];
            float tm = fmaxf(fmaxf(pm[0][t], pm[1][t]), fmaxf(pm[2][t], pm[3][t]));
            d_sa_avg[b * NPIX + n0 + t] = ts * (1.0f / CC);
            d_sa_max[b * NPIX + n0 + t] = tm;
        }
    }

    // ================= PAM fallback (uniform branch; benchmark: g==0) ========
    if (g != 0.0f) {
        grid_barrier();
        for (int bn = blk * NTHR + t; bn < BB * NPIX; bn += NBLK * NTHR) {
            const int bb = bn >> 12, n = bn & (NPIX - 1);
            const float* xb = x + (size_t)bb * CC * NPIX + n;
            float qa[CR], ka[CR];
            #pragma unroll
            for (int r = 0; r < CR; r++) { qa[r] = qbias[r]; ka[r] = kbias[r]; }
            for (int c = 0; c < CC; c++) {
                const float xv = xb[c * NPIX];
                #pragma unroll
                for (int r = 0; r < CR; r++) {
                    qa[r] += xv * qw[r * CC + c];
                    ka[r] += xv * kw[r * CC + c];
                }
            }
            #pragma unroll
            for (int r = 0; r < CR; r++) {
                d_q[(bb * CR + r) * NPIX + n] = qa[r];
                d_k[(bb * CR + r) * NPIX + n] = ka[r];
            }
        }
        for (int bcn = blk * NTHR + t; bcn < BB * CC * NPIX; bcn += NBLK * NTHR) {
            const int bc = bcn >> 12;
            const int bb = bc >> 6, c = bc & 63, n = bcn & (NPIX - 1);
            const float* xb = x + (size_t)bb * CC * NPIX + n;
            float acc = vbias[c];
            for (int cc = 0; cc < CC; cc++) acc += xb[cc * NPIX] * vw[c * CC + cc];
            d_v[bcn] = acc;
        }
        grid_barrier();
        for (int row = blk; row < BB * NPIX; row += NBLK) {
            const int bb = row >> 12;
            const int i  = row & (NPIX - 1);
            float qr[CR];
            #pragma unroll
            for (int r = 0; r < CR; r++) qr[r] = __ldcg(&d_q[(bb * CR + r) * NPIX + i]);
            float mx = -INFINITY;
            for (int j = t; j < NPIX; j += NTHR) {
                float e = 0.0f;
                #pragma unroll
                for (int r = 0; r < CR; r++) e += qr[r] * __ldcg(&d_k[(bb * CR + r) * NPIX + j]);
                att[j] = e;
                mx = fmaxf(mx, e);
            }
            red[t] = mx; __syncthreads();
            for (int s = NTHR / 2; s; s >>= 1) {
                if (t < s) red[t] = fmaxf(red[t], red[t + s]);
                __syncthreads();
            }
            mx = red[0]; __syncthreads();
            float sum = 0.0f;
            for (int j = t; j < NPIX; j += NTHR) {
                const float e = expf(att[j] - mx);
                att[j] = e;
                sum += e;
            }
            red[t] = sum; __syncthreads();
            for (int s = NTHR / 2; s; s >>= 1) {
                if (t < s) red[t] += red[t + s];
                __syncthreads();
            }
            const float inv = 1.0f / red[0]; __syncthreads();
            for (int c = 0; c < CC; c++) {
                float acc = 0.0f;
                for (int j = t; j < NPIX; j += NTHR)
                    acc += att[j] * __ldcg(&d_v[(bb * CC + c) * NPIX + j]);
                red[t] = acc; __syncthreads();
                for (int s = NTHR / 2; s; s >>= 1) {
                    if (t < s) red[t] += red[t + s];
                    __syncthreads();
                }
                if (t == 0) d_pam[(bb * CC + c) * NPIX + i] = red[0] * inv;
                __syncthreads();
            }
        }
    }

    grid_barrier();

    // ================= Phase C: 7x7 conv + sigmoid + final combine ==========
    if (t < 98) wgt[t] = sw[t];
    const int h0 = chunk << 2;
    for (int i = t; i < 700; i += NTHR) {
        const int r = i / 70, cidx = i % 70;
        const int gh = h0 - 3 + r, gw = cidx - 3;
        float a = 0.0f, mv = 0.0f;
        if (gh >= 0 && gh < HH && (unsigned)gw < (unsigned)WWD) {
            const int gi = b * NPIX + gh * WWD + gw;
            a  = __ldcg(&d_sa_avg[gi]);
            mv = __ldcg(&d_sa_max[gi]);
        }
        s_avg[r][cidx] = a;
        s_max[r][cidx] = mv;
    }
    __syncthreads();
    if (t < 256) {
        const int h = t >> 6, w = t & 63;
        float acc = 0.0f;
        #pragma unroll
        for (int kh = 0; kh < 7; kh++)
            #pragma unroll
            for (int kw2 = 0; kw2 < 7; kw2++)
                acc += s_avg[h + kh][w + kw2] * wgt[kh * 7 + kw2]
                     + s_max[h + kh][w + kw2] * wgt[49 + kh * 7 + kw2];
        mask[t] = 1.0f / (1.0f + __expf(-acc));
    }
    __syncthreads();
    {
        const int lane4 = t & 63;   // float4 index within the 256-px chunk
        const int c0    = t >> 6;   // 0..15
        const float4 m4 = reinterpret_cast<const float4*>(mask)[lane4];
        const size_t base4 = (size_t)b * CC * (NPIX / 4) + (size_t)(n0 / 4) + lane4;
        if (g == 0.0f) {
            #pragma unroll
            for (int k = 0; k < 4; k++) {
                const int c = c0 + 16 * k;
                const size_t idx4 = base4 + (size_t)c * (NPIX / 4);
                const float4 xv = reinterpret_cast<const float4*>(x)[idx4];
                const float cav = ca[c];
                float4 o;
                o.x = xv.x * (1.0f + cav * m4.x);
                o.y = xv.y * (1.0f + cav * m4.y);
                o.z = xv.z * (1.0f + cav * m4.z);
                o.w = xv.w * (1.0f + cav * m4.w);
                __stcs(&reinterpret_cast<float4*>(out)[idx4], o);
            }
        } else {
            #pragma unroll
            for (int k = 0; k < 4; k++) {
                const int c = c0 + 16 * k;
                const size_t idx4 = base4 + (size_t)c * (NPIX / 4);
                const float4 xv = reinterpret_cast<const float4*>(x)[idx4];
                const float4 pv = reinterpret_cast<const float4*>(d_pam)[idx4];
                const float cav = ca[c];
                float4 o;
                o.x = xv.x * (1.0f + cav * m4.x) + g * pv.x;
                o.y = xv.y * (1.0f + cav * m4.y) + g * pv.y;
                o.z = xv.z * (1.0f + cav * m4.z) + g * pv.z;
                o.w = xv.w * (1.0f + cav * m4.w) + g * pv.w;
                __stcs(&reinterpret_cast<float4*>(out)[idx4], o);
            }
        }
    }
}

// ---------------- launch ----------------
extern "C" void kernel_launch(void* const* d_in, const int* in_sizes, int n_in,
                              void* d_out, int out_size) {
    const float* x     = (const float*)d_in[0];
    const float* fc1_w = (const float*)d_in[1];
    const float* fc2_w = (const float*)d_in[2];
    const float* q_w   = (const float*)d_in[3];
    const float* q_b   = (const float*)d_in[4];
    const float* k_w   = (const float*)d_in[5];
    const float* k_b   = (const float*)d_in[6];
    const float* v_w   = (const float*)d_in[7];
    const float* v_b   = (const float*)d_in[8];
    const float* gamma = (const float*)d_in[9];
    const float* sa_w  = (const float*)d_in[10];
    float* out = (float*)d_out;

    k_pcbam<<<NBLK, NTHR>>>(x, fc1_w, fc2_w, q_w, q_b, k_w, k_b, v_w, v_b,
                            gamma, sa_w, out);
}

// round 16
// speedup vs baseline: 1.0691x; 1.0346x over previous
#include <cuda_runtime.h>
#include <math.h>

#define BB   8
#define CC   64
#define CR   8
#define HH   64
#define WWD  64
#define NPIX 4096   // HH*WWD
#define NBLK 128    // persistent grid: must be <= SM count (148)
#define NTHR 1024
#define BPB  16     // blocks per batch

// ---------------- device scratch (static, no allocation) ----------------
__device__ float d_avg[BB * CC];
__device__ float d_maxv[BB * CC];
__device__ float d_sa_avg[BB * NPIX];
__device__ float d_sa_max[BB * NPIX];
// PAM fallback scratch (only written when gamma != 0)
__device__ float d_q[BB * CR * NPIX];
__device__ float d_k[BB * CR * NPIX];
__device__ float d_v[BB * CC * NPIX];
__device__ __align__(16) float d_pam[BB * CC * NPIX];
// barrier tickets (monotonic; safe across graph replays)
__device__ unsigned long long g_bar;            // global (fallback only)
__device__ unsigned long long g_bar_b[BB];      // per-batch, 16 blocks each

// Global barrier: all NBLK blocks co-resident (1 CTA/SM) -> deadlock-free spin.
__device__ __forceinline__ void grid_barrier() {
    __syncthreads();
    if (threadIdx.x == 0) {
        __threadfence();
        const unsigned long long t = atomicAdd(&g_bar, 1ULL);
        const unsigned long long release = (t / NBLK + 1ULL) * (unsigned long long)NBLK;
        volatile unsigned long long* p = &g_bar;
        while (*p < release) { }
    }
    __syncthreads();
}

// Per-batch barrier: syncs only the 16 blocks of one batch. All deps in
// phases A->B->C are intra-batch, so this is sufficient and far cheaper
// (16-way arrival spread instead of 128-way; 8 decoupled pipelines).
__device__ __forceinline__ void batch_barrier(int b) {
    __syncthreads();
    if (threadIdx.x == 0) {
        __threadfence();
        const unsigned long long t = atomicAdd(&g_bar_b[b], 1ULL);
        const unsigned long long release = (t / BPB + 1ULL) * (unsigned long long)BPB;
        volatile unsigned long long* p = &g_bar_b[b];
        while (*p < release) { }
    }
    __syncthreads();
}

__global__ void __launch_bounds__(NTHR, 1)
k_pcbam(const float* __restrict__ x,
        const float* __restrict__ fc1,   // [CR, C]
        const float* __restrict__ fc2,   // [C, CR]
        const float* __restrict__ qw, const float* __restrict__ qbias,
        const float* __restrict__ kw, const float* __restrict__ kbias,
        const float* __restrict__ vw, const float* __restrict__ vbias,
        const float* __restrict__ gamma,
        const float* __restrict__ sw,    // [2,7,7]
        float* __restrict__ out) {
    const int blk = blockIdx.x;   // 0..127
    const int t   = threadIdx.x;  // 0..1023
    const int b     = blk >> 4;   // batch (phase A rows blk*4.. are in this batch too)
    const int chunk = blk & 15;   // 256-pixel chunk
    const int n0    = chunk << 8;

    __shared__ float red_s[32], red_m[32];
    __shared__ float ca[CC], h_avg[CR], h_mx[CR];
    __shared__ float ps[4][256], pm[4][256];
    __shared__ float s_avg[10][70], s_max[10][70];
    __shared__ float wgt[98];
    __shared__ __align__(16) float mask[256];
    __shared__ float att[NPIX];    // PAM fallback only
    __shared__ float red[NTHR];    // PAM fallback only

    const float g = gamma[0];
    const int wid = t >> 5, lid = t & 31;

    // ================= Phase A: per-(b,c) mean & max over HW =================
    // block blk reduces rows bc = blk*4 .. blk*4+3 (all within batch b).
    {
        const int row  = t >> 8;        // 0..3
        const int rtid = t & 255;
        const int bc   = blk * 4 + row;
        const float4* xp = reinterpret_cast<const float4*>(x + (size_t)bc * NPIX);
        float s = 0.0f, m = -INFINITY;
        #pragma unroll
        for (int j = 0; j < 4; j++) {
            const float4 v = xp[rtid + j * 256];
            s += (v.x + v.y) + (v.z + v.w);
            m = fmaxf(m, fmaxf(fmaxf(v.x, v.y), fmaxf(v.z, v.w)));
        }
        #pragma unroll
        for (int off = 16; off; off >>= 1) {
            s += __shfl_down_sync(0xffffffffu, s, off);
            m  = fmaxf(m, __shfl_down_sync(0xffffffffu, m, off));
        }
        if (lid == 0) { red_s[wid] = s; red_m[wid] = m; }
        __syncthreads();
        if (rtid == 0) {
            float ts = 0.0f, tm = -INFINITY;
            #pragma unroll
            for (int w = 0; w < 8; w++) {
                ts += red_s[row * 8 + w];
                tm = fmaxf(tm, red_m[row * 8 + w]);
            }
            d_avg[bc]  = ts * (1.0f / NPIX);
            d_maxv[bc] = tm;
        }
    }

    batch_barrier(b);

    // ================= Phase B: fused MLP + spatial stats =================
    if (t < CR) {
        float ha = 0.0f, hm = 0.0f;
        #pragma unroll
        for (int c = 0; c < CC; c++) {
            const float w = fc1[t * CC + c];
            ha += __ldcg(&d_avg[b * CC + c])  * w;
            hm += __ldcg(&d_maxv[b * CC + c]) * w;
        }
        h_avg[t] = fmaxf(ha, 0.0f);
        h_mx[t]  = fmaxf(hm, 0.0f);
    }
    __syncthreads();
    if (t < CC) {
        float o = 0.0f;
        #pragma unroll
        for (int r = 0; r < CR; r++)
            o += (h_avg[r] + h_mx[r]) * fc2[t * CR + r];
        ca[t] = 1.0f / (1.0f + __expf(-o));
    }
    __syncthreads();
    {
        const int px  = t & 255;
        const int grp = t >> 8;
        const int n   = n0 + px;
        const float* xb = x + (size_t)b * CC * NPIX + n;
        float s = 0.0f, m = -INFINITY;
        #pragma unroll
        for (int cc = 0; cc < 16; cc++) {
            const int c = grp * 16 + cc;
            const float v = xb[c * NPIX] * ca[c];
            s += v;
            m = fmaxf(m, v);
        }
        ps[grp][px] = s;
        pm[grp][px] = m;
        __syncthreads();
        if (t < 256) {
            float ts = ps[0][t] + ps[1][t] + ps[2][t] + ps[3][t];
            float tm = fmaxf(fmaxf(pm[0][t], pm[1][t]), fmaxf(pm[2][t], pm[3][t]));
            d_sa_avg[b * NPIX + n0 + t] = ts * (1.0f / CC);
            d_sa_max[b * NPIX + n0 + t] = tm;
        }
    }

    // ================= PAM fallback (uniform branch; benchmark: g==0) ========
    if (g != 0.0f) {
        grid_barrier();   // attention mixes batches -> global sync required
        for (int bn = blk * NTHR + t; bn < BB * NPIX; bn += NBLK * NTHR) {
            const int bb = bn >> 12, n = bn & (NPIX - 1);
            const float* xb = x + (size_t)bb * CC * NPIX + n;
            float qa[CR], ka[CR];
            #pragma unroll
            for (int r = 0; r < CR; r++) { qa[r] = qbias[r]; ka[r] = kbias[r]; }
            for (int c = 0; c < CC; c++) {
                const float xv = xb[c * NPIX];
                #pragma unroll
                for (int r = 0; r < CR; r++) {
                    qa[r] += xv * qw[r * CC + c];
                    ka[r] += xv * kw[r * CC + c];
                }
            }
            #pragma unroll
            for (int r = 0; r < CR; r++) {
                d_q[(bb * CR + r) * NPIX + n] = qa[r];
                d_k[(bb * CR + r) * NPIX + n] = ka[r];
            }
        }
        for (int bcn = blk * NTHR + t; bcn < BB * CC * NPIX; bcn += NBLK * NTHR) {
            const int bc = bcn >> 12;
            const int bb = bc >> 6, c = bc & 63, n = bcn & (NPIX - 1);
            const float* xb = x + (size_t)bb * CC * NPIX + n;
            float acc = vbias[c];
            for (int cc = 0; cc < CC; cc++) acc += xb[cc * NPIX] * vw[c * CC + cc];
            d_v[bcn] = acc;
        }
        grid_barrier();
        for (int row = blk; row < BB * NPIX; row += NBLK) {
            const int bb = row >> 12;
            const int i  = row & (NPIX - 1);
            float qr[CR];
            #pragma unroll
            for (int r = 0; r < CR; r++) qr[r] = __ldcg(&d_q[(bb * CR + r) * NPIX + i]);
            float mx = -INFINITY;
            for (int j = t; j < NPIX; j += NTHR) {
                float e = 0.0f;
                #pragma unroll
                for (int r = 0; r < CR; r++) e += qr[r] * __ldcg(&d_k[(bb * CR + r) * NPIX + j]);
                att[j] = e;
                mx = fmaxf(mx, e);
            }
            red[t] = mx; __syncthreads();
            for (int s = NTHR / 2; s; s >>= 1) {
                if (t < s) red[t] = fmaxf(red[t], red[t + s]);
                __syncthreads();
            }
            mx = red[0]; __syncthreads();
            float sum = 0.0f;
            for (int j = t; j < NPIX; j += NTHR) {
                const float e = expf(att[j] - mx);
                att[j] = e;
                sum += e;
            }
            red[t] = sum; __syncthreads();
            for (int s = NTHR / 2; s; s >>= 1) {
                if (t < s) red[t] += red[t + s];
                __syncthreads();
            }
            const float inv = 1.0f / red[0]; __syncthreads();
            for (int c = 0; c < CC; c++) {
                float acc = 0.0f;
                for (int j = t; j < NPIX; j += NTHR)
                    acc += att[j] * __ldcg(&d_v[(bb * CC + c) * NPIX + j]);
                red[t] = acc; __syncthreads();
                for (int s = NTHR / 2; s; s >>= 1) {
                    if (t < s) red[t] += red[t + s];
                    __syncthreads();
                }
                if (t == 0) d_pam[(bb * CC + c) * NPIX + i] = red[0] * inv;
                __syncthreads();
            }
        }
        grid_barrier();
    } else {
        batch_barrier(b);   // conv halo needs same-batch sa rows only
    }

    // ================= Phase C: 7x7 conv + sigmoid + final combine ==========
    if (t < 98) wgt[t] = sw[t];
    const int h0 = chunk << 2;
    for (int i = t; i < 700; i += NTHR) {
        const int r = i / 70, cidx = i % 70;
        const int gh = h0 - 3 + r, gw = cidx - 3;
        float a = 0.0f, mv = 0.0f;
        if (gh >= 0 && gh < HH && (unsigned)gw < (unsigned)WWD) {
            const int gi = b * NPIX + gh * WWD + gw;
            a  = __ldcg(&d_sa_avg[gi]);
            mv = __ldcg(&d_sa_max[gi]);
        }
        s_avg[r][cidx] = a;
        s_max[r][cidx] = mv;
    }
    __syncthreads();
    if (t < 256) {
        const int h = t >> 6, w = t & 63;
        float acc = 0.0f;
        #pragma unroll
        for (int kh = 0; kh < 7; kh++)
            #pragma unroll
            for (int kw2 = 0; kw2 < 7; kw2++)
                acc += s_avg[h + kh][w + kw2] * wgt[kh * 7 + kw2]
                     + s_max[h + kh][w + kw2] * wgt[49 + kh * 7 + kw2];
        mask[t] = 1.0f / (1.0f + __expf(-acc));
    }
    __syncthreads();
    {
        const int lane4 = t & 63;
        const int c0    = t >> 6;
        const float4 m4 = reinterpret_cast<const float4*>(mask)[lane4];
        const size_t base4 = (size_t)b * CC * (NPIX / 4) + (size_t)(n0 / 4) + lane4;
        if (g == 0.0f) {
            #pragma unroll
            for (int k = 0; k < 4; k++) {
                const int c = c0 + 16 * k;
                const size_t idx4 = base4 + (size_t)c * (NPIX / 4);
                const float4 xv = reinterpret_cast<const float4*>(x)[idx4];
                const float cav = ca[c];
                float4 o;
                o.x = xv.x * (1.0f + cav * m4.x);
                o.y = xv.y * (1.0f + cav * m4.y);
                o.z = xv.z * (1.0f + cav * m4.z);
                o.w = xv.w * (1.0f + cav * m4.w);
                __stcs(&reinterpret_cast<float4*>(out)[idx4], o);
            }
        } else {
            #pragma unroll
            for (int k = 0; k < 4; k++) {
                const int c = c0 + 16 * k;
                const size_t idx4 = base4 + (size_t)c * (NPIX / 4);
                const float4 xv = reinterpret_cast<const float4*>(x)[idx4];
                const float4 pv = reinterpret_cast<const float4*>(d_pam)[idx4];
                const float cav = ca[c];
                float4 o;
                o.x = xv.x * (1.0f + cav * m4.x) + g * pv.x;
                o.y = xv.y * (1.0f + cav * m4.y) + g * pv.y;
                o.z = xv.z * (1.0f + cav * m4.z) + g * pv.z;
                o.w = xv.w * (1.0f + cav * m4.w) + g * pv.w;
                __stcs(&reinterpret_cast<float4*>(out)[idx4], o);
            }
        }
    }
}

// ---------------- launch ----------------
extern "C" void kernel_launch(void* const* d_in, const int* in_sizes, int n_in,
                              void* d_out, int out_size) {
    const float* x     = (const float*)d_in[0];
    const float* fc1_w = (const float*)d_in[1];
    const float* fc2_w = (const float*)d_in[2];
    const float* q_w   = (const float*)d_in[3];
    const float* q_b   = (const float*)d_in[4];
    const float* k_w   = (const float*)d_in[5];
    const float* k_b   = (const float*)d_in[6];
    const float* v_w   = (const float*)d_in[7];
    const float* v_b   = (const float*)d_in[8];
    const float* gamma = (const float*)d_in[9];
    const float* sa_w  = (const float*)d_in[10];
    float* out = (float*)d_out;

    k_pcbam<<<NBLK, NTHR>>>(x, fc1_w, fc2_w, q_w, q_b, k_w, k_b, v_w, v_b,
                            gamma, sa_w, out);
}